// round 1
// baseline (speedup 1.0000x reference)
#include <cuda_runtime.h>

#define NS 1024
#define NQ 8192
#define DD 256
#define EPS 0.05f
#define INV_EPS 20.0f
#define THRESH 1e-3f
#define MAXIT 100
// log(1/Ns + 1e-8), log(1/Nq + 1e-8); uniform offsets cancel in the softmax,
// so limited precision here is harmless.
#define LOG_MU -6.93146157f
#define LOG_NU -9.01083122f

// Scratch (allocation-free rule: __device__ globals)
__device__ float g_Ck[(size_t)NS * NQ];   // -C/eps, row-major [NS][NQ]  (32 MB)
__device__ float g_CkT[(size_t)NQ * NS];  // transpose [NQ][NS]; reused as split-K partials later
__device__ float g_us[NS];
__device__ float g_vs[NQ];
__device__ float g_r[NS];   // |x_i|^2 / eps
__device__ float g_c[NQ];   // |y_j|^2 / eps
__device__ float g_ls[NS];  // final row logsumexp
__device__ float g_err[MAXIT + 1];
__device__ int g_done;

// ---------------------------------------------------------------- init
__global__ void k_init() {
    int t = threadIdx.x;
    if (t == 0) g_done = 0;
    for (int i = t; i < NQ; i += 1024) g_vs[i] = 0.f;
    for (int i = t; i < NS; i += 1024) g_us[i] = 0.f;
    if (t <= MAXIT) g_err[t] = 0.f;
}

// ---------------------------------------------------------------- row norms
__global__ void k_norms(const float* __restrict__ X, const float* __restrict__ Y) {
    int gw = (blockIdx.x * blockDim.x + threadIdx.x) >> 5;
    int l = threadIdx.x & 31;
    if (gw >= NS + NQ) return;
    const float* p = (gw < NS) ? (X + (size_t)gw * DD) : (Y + (size_t)(gw - NS) * DD);
    const float4* p4 = (const float4*)p;
    float s = 0.f;
#pragma unroll
    for (int q = 0; q < 2; q++) {
        float4 a = p4[l + 32 * q];
        s += a.x * a.x + a.y * a.y + a.z * a.z + a.w * a.w;
    }
#pragma unroll
    for (int o = 16; o; o >>= 1) s += __shfl_xor_sync(0xffffffffu, s, o);
    if (l == 0) {
        if (gw < NS) g_r[gw] = s * INV_EPS;
        else         g_c[gw - NS] = s * INV_EPS;
    }
}

// ---------------------------------------------------------------- Ck = (2 x.y - |x|^2 - |y|^2)/eps
__global__ __launch_bounds__(256) void k_gemm_ck(const float* __restrict__ X,
                                                 const float* __restrict__ Y) {
    __shared__ float As[16][128];
    __shared__ float Bs[16][128];
    int tid = threadIdx.x;
    int tx = tid & 15, ty = tid >> 4;
    int i0 = blockIdx.y * 128, j0 = blockIdx.x * 128;
    float acc[8][8];
#pragma unroll
    for (int m = 0; m < 8; m++)
#pragma unroll
        for (int n = 0; n < 8; n++) acc[m][n] = 0.f;

    for (int k0 = 0; k0 < DD; k0 += 16) {
#pragma unroll
        for (int q = 0; q < 2; q++) {
            int lt = tid + 256 * q;
            int row = lt >> 2, kq = (lt & 3) << 2;
            float4 a = *(const float4*)(X + (size_t)(i0 + row) * DD + k0 + kq);
            As[kq + 0][row] = a.x; As[kq + 1][row] = a.y;
            As[kq + 2][row] = a.z; As[kq + 3][row] = a.w;
            float4 b = *(const float4*)(Y + (size_t)(j0 + row) * DD + k0 + kq);
            Bs[kq + 0][row] = b.x; Bs[kq + 1][row] = b.y;
            Bs[kq + 2][row] = b.z; Bs[kq + 3][row] = b.w;
        }
        __syncthreads();
#pragma unroll
        for (int k = 0; k < 16; k++) {
            float af[8], bf[8];
#pragma unroll
            for (int m = 0; m < 8; m++) af[m] = As[k][ty * 8 + m];
#pragma unroll
            for (int n = 0; n < 8; n++) bf[n] = Bs[k][tx * 8 + n];
#pragma unroll
            for (int m = 0; m < 8; m++)
#pragma unroll
                for (int n = 0; n < 8; n++) acc[m][n] += af[m] * bf[n];
        }
        __syncthreads();
    }
#pragma unroll
    for (int m = 0; m < 8; m++) {
        int i = i0 + ty * 8 + m;
        float ri = g_r[i];
#pragma unroll
        for (int n0 = 0; n0 < 8; n0 += 4) {
            int j = j0 + tx * 8 + n0;
            float4 o;
            o.x = acc[m][n0 + 0] * (2.f * INV_EPS) - ri - g_c[j + 0];
            o.y = acc[m][n0 + 1] * (2.f * INV_EPS) - ri - g_c[j + 1];
            o.z = acc[m][n0 + 2] * (2.f * INV_EPS) - ri - g_c[j + 2];
            o.w = acc[m][n0 + 3] * (2.f * INV_EPS) - ri - g_c[j + 3];
            *(float4*)(g_Ck + (size_t)i * NQ + j) = o;
        }
    }
}

// ---------------------------------------------------------------- transpose Ck -> CkT
__global__ void k_transpose() {
    __shared__ float tile[32][33];
    int bx = blockIdx.x, by = blockIdx.y;  // j-tile, i-tile
    int txl = threadIdx.x, tyl = threadIdx.y;
    int j = bx * 32 + txl;
#pragma unroll
    for (int r = tyl; r < 32; r += 8)
        tile[r][txl] = g_Ck[(size_t)(by * 32 + r) * NQ + j];
    __syncthreads();
    int i = by * 32 + txl;
#pragma unroll
    for (int r = tyl; r < 32; r += 8)
        g_CkT[(size_t)(bx * 32 + r) * NS + i] = tile[txl][r];
}

// ---------------------------------------------------------------- lse helpers
__device__ __forceinline__ void lse_combine(float& m, float& s, float om, float os) {
    float nm = fmaxf(m, om);
    s = s * __expf(m - nm) + os * __expf(om - nm);
    m = nm;
}

// ---------------------------------------------------------------- row pass (u-update / final lse)
// mode 0: Sinkhorn u-update with convergence bookkeeping. mode 1: write g_ls (always runs).
__global__ __launch_bounds__(256) void k_rowpass(int t, int mode) {
    if (mode == 0) {
        bool conv = (t > 0) && (g_err[t - 1] < THRESH);
        if (conv) g_done = 1;
        if (conv || g_done) return;
    }
    int tid = threadIdx.x;
    int i = blockIdx.x;
    const float4* c4 = (const float4*)(g_Ck + (size_t)i * NQ);
    const float4* v4 = (const float4*)g_vs;
    float v[32];
#pragma unroll
    for (int sIdx = 0; sIdx < 8; sIdx++) {
        float4 a = c4[tid + 256 * sIdx];
        float4 b = v4[tid + 256 * sIdx];
        v[4 * sIdx + 0] = a.x + b.x; v[4 * sIdx + 1] = a.y + b.y;
        v[4 * sIdx + 2] = a.z + b.z; v[4 * sIdx + 3] = a.w + b.w;
    }
    float m = v[0];
#pragma unroll
    for (int k = 1; k < 32; k++) m = fmaxf(m, v[k]);
    float s = 0.f;
#pragma unroll
    for (int k = 0; k < 32; k++) s += __expf(v[k] - m);
#pragma unroll
    for (int o = 16; o; o >>= 1)
        lse_combine(m, s, __shfl_xor_sync(0xffffffffu, m, o), __shfl_xor_sync(0xffffffffu, s, o));
    __shared__ float sm[8], ss[8];
    int w = tid >> 5, l = tid & 31;
    if (l == 0) { sm[w] = m; ss[w] = s; }
    __syncthreads();
    if (w == 0) {
        m = sm[l & 7]; s = ss[l & 7];  // disjoint 8-lane groups; only group 0 matters
#pragma unroll
        for (int o = 4; o; o >>= 1)
            lse_combine(m, s, __shfl_xor_sync(0xffffffffu, m, o), __shfl_xor_sync(0xffffffffu, s, o));
        if (l == 0) {
            float lse = m + __logf(s);
            if (mode == 0) {
                float un = LOG_MU - lse;
                float uo = g_us[i];
                g_us[i] = un;
                atomicAdd(&g_err[t], EPS * fabsf(un - uo));
            } else {
                g_ls[i] = lse;
            }
        }
    }
}

// ---------------------------------------------------------------- col pass (v-update), warp per column
__global__ __launch_bounds__(256) void k_colpass(int t) {
    if (g_done) return;
    int w = threadIdx.x >> 5, l = threadIdx.x & 31;
    int j = (blockIdx.x << 3) + w;
    const float4* c4 = (const float4*)(g_CkT + (size_t)j * NS);
    const float4* u4 = (const float4*)g_us;
    float v[32];
#pragma unroll
    for (int sIdx = 0; sIdx < 8; sIdx++) {
        float4 a = c4[l + 32 * sIdx];
        float4 b = u4[l + 32 * sIdx];
        v[4 * sIdx + 0] = a.x + b.x; v[4 * sIdx + 1] = a.y + b.y;
        v[4 * sIdx + 2] = a.z + b.z; v[4 * sIdx + 3] = a.w + b.w;
    }
    float m = v[0];
#pragma unroll
    for (int k = 1; k < 32; k++) m = fmaxf(m, v[k]);
    float s = 0.f;
#pragma unroll
    for (int k = 0; k < 32; k++) s += __expf(v[k] - m);
#pragma unroll
    for (int o = 16; o; o >>= 1)
        lse_combine(m, s, __shfl_xor_sync(0xffffffffu, m, o), __shfl_xor_sync(0xffffffffu, s, o));
    if (l == 0) g_vs[j] = LOG_NU - (m + __logf(s));
}

// ---------------------------------------------------------------- P = exp(Ck + vs - ls) in place
__global__ void k_makeP() {
    int idx = blockIdx.x * blockDim.x + threadIdx.x;  // float4 index; total NS*NQ/4
    int i = idx >> 11;       // NQ/4 = 2048 float4 per row
    int j4 = idx & 2047;
    float4 c = ((const float4*)g_Ck)[idx];
    float4 vv = ((const float4*)g_vs)[j4];
    float ls = g_ls[i];
    float4 o;
    o.x = __expf(c.x + vv.x - ls);
    o.y = __expf(c.y + vv.y - ls);
    o.z = __expf(c.z + vv.z - ls);
    o.w = __expf(c.w + vv.w - ls);
    ((float4*)g_Ck)[idx] = o;
}

// ---------------------------------------------------------------- O = P @ Y, split-K into g_CkT
#define SPLITK 4
__global__ __launch_bounds__(256) void k_outgemm(const float* __restrict__ Y) {
    __shared__ float As[16][64];
    __shared__ float Bs[16][64];
    int tid = threadIdx.x, tx = tid & 15, ty = tid >> 4;
    int bn = blockIdx.x, bm = blockIdx.y, ks = blockIdx.z;
    const float* P = g_Ck;
    float* part = g_CkT;  // reuse: transpose no longer needed
    float acc[4][4];
#pragma unroll
    for (int m = 0; m < 4; m++)
#pragma unroll
        for (int n = 0; n < 4; n++) acc[m][n] = 0.f;

    int prow = tid >> 2, pk = (tid & 3) << 2;
    int yrow = tid >> 4, yc = (tid & 15) << 2;
    int kbeg = ks * (NQ / SPLITK), kend = kbeg + NQ / SPLITK;
    for (int k0 = kbeg; k0 < kend; k0 += 16) {
        float4 a = *(const float4*)(P + (size_t)(bm * 64 + prow) * NQ + k0 + pk);
        As[pk + 0][prow] = a.x; As[pk + 1][prow] = a.y;
        As[pk + 2][prow] = a.z; As[pk + 3][prow] = a.w;
        float4 b = *(const float4*)(Y + (size_t)(k0 + yrow) * DD + bn * 64 + yc);
        *(float4*)&Bs[yrow][yc] = b;
        __syncthreads();
#pragma unroll
        for (int k = 0; k < 16; k++) {
            float af[4], bf[4];
#pragma unroll
            for (int m = 0; m < 4; m++) af[m] = As[k][ty * 4 + m];
#pragma unroll
            for (int n = 0; n < 4; n++) bf[n] = Bs[k][tx * 4 + n];
#pragma unroll
            for (int m = 0; m < 4; m++)
#pragma unroll
                for (int n = 0; n < 4; n++) acc[m][n] += af[m] * bf[n];
        }
        __syncthreads();
    }
#pragma unroll
    for (int m = 0; m < 4; m++) {
        float4 o;
        o.x = acc[m][0]; o.y = acc[m][1]; o.z = acc[m][2]; o.w = acc[m][3];
        *(float4*)(part + (size_t)ks * NS * DD + (size_t)(bm * 64 + ty * 4 + m) * DD + bn * 64 + tx * 4) = o;
    }
}

// ---------------------------------------------------------------- reduce split-K + append z_query
__global__ void k_finalize(float* __restrict__ out, const float* __restrict__ Y) {
    int idx = blockIdx.x * blockDim.x + threadIdx.x;  // float4 index over (NS+NQ)*DD/4
    const float4* part = (const float4*)g_CkT;
    float4* o4 = (float4*)out;
    if (idx < NS * DD / 4) {
        float4 a = part[idx], b = part[idx + 65536], c = part[idx + 131072], d = part[idx + 196608];
        float4 r;
        r.x = a.x + b.x + c.x + d.x;
        r.y = a.y + b.y + c.y + d.y;
        r.z = a.z + b.z + c.z + d.z;
        r.w = a.w + b.w + c.w + d.w;
        o4[idx] = r;
    } else {
        o4[idx] = ((const float4*)Y)[idx - NS * DD / 4];
    }
}

// ----------------------------------------------------------------
extern "C" void kernel_launch(void* const* d_in, const int* in_sizes, int n_in,
                              void* d_out, int out_size) {
    const float* zs = (const float*)d_in[0];
    const float* zq = (const float*)d_in[1];
    if (n_in >= 2 && in_sizes[0] == NQ * DD && in_sizes[1] == NS * DD) {
        const float* t = zs; zs = zq; zq = t;  // tolerate either input order
    }
    k_init<<<1, 1024>>>();
    k_norms<<<(NS + NQ) * 32 / 256, 256>>>(zs, zq);
    k_gemm_ck<<<dim3(NQ / 128, NS / 128), 256>>>(zs, zq);
    k_transpose<<<dim3(NQ / 32, NS / 32), dim3(32, 8)>>>();
    for (int t = 0; t < MAXIT; t++) {
        k_rowpass<<<NS, 256>>>(t, 0);
        k_colpass<<<NS, 256>>>(t);
    }
    k_rowpass<<<NS, 256>>>(0, 1);          // final row lse -> g_ls
    k_makeP<<<NS * NQ / 4 / 256, 256>>>();
    k_outgemm<<<dim3(DD / 64, NS / 64, SPLITK), 256>>>(zq);
    k_finalize<<<(NS + NQ) * DD / 4 / 256, 256>>>((float*)d_out, zq);
}

// round 5
// speedup vs baseline: 1.7758x; 1.7758x over previous
#include <cuda_runtime.h>

#define NS 1024
#define NQ 8192
#define DD 256
#define EPS 0.05f
#define INV_EPS 20.0f
#define THRESH 1e-3f
#define MAXIT 100
#define LOG_MU -6.93146157f
#define LOG_NU -9.01083122f
#define NBLK 148
#define NWARP_TOT (NBLK * 32)

// Scratch (allocation-free rule: __device__ globals)
__device__ float g_Ck[(size_t)NS * NQ];   // -C/eps, row-major [NS][NQ]  (32 MB)
__device__ float g_CkT[(size_t)NQ * NS];  // transpose; reused as split-K partials later
__device__ float g_us[NS];
__device__ float g_vs[NQ];
__device__ float g_r[NS];
__device__ float g_c[NQ];
__device__ float g_ls[NS];
__device__ float g_err[MAXIT];
__device__ int g_bar_count;
__device__ volatile int g_bar_sense;

// ---------------------------------------------------------------- init
__global__ void k_init() {
    int t = threadIdx.x;
    if (t == 0) { g_bar_count = 0; g_bar_sense = 0; }
    for (int i = t; i < NQ; i += 1024) g_vs[i] = 0.f;
    for (int i = t; i < NS; i += 1024) g_us[i] = 0.f;
    for (int i = t; i < MAXIT; i += 1024) g_err[i] = 0.f;
}

// ---------------------------------------------------------------- row norms
__global__ void k_norms(const float* __restrict__ X, const float* __restrict__ Y) {
    int gw = (blockIdx.x * blockDim.x + threadIdx.x) >> 5;
    int l = threadIdx.x & 31;
    if (gw >= NS + NQ) return;
    const float* p = (gw < NS) ? (X + (size_t)gw * DD) : (Y + (size_t)(gw - NS) * DD);
    const float4* p4 = (const float4*)p;
    float s = 0.f;
#pragma unroll
    for (int q = 0; q < 2; q++) {
        float4 a = p4[l + 32 * q];
        s += a.x * a.x + a.y * a.y + a.z * a.z + a.w * a.w;
    }
#pragma unroll
    for (int o = 16; o; o >>= 1) s += __shfl_xor_sync(0xffffffffu, s, o);
    if (l == 0) {
        if (gw < NS) g_r[gw] = s * INV_EPS;
        else         g_c[gw - NS] = s * INV_EPS;
    }
}

// ---------------------------------------------------------------- Ck = (2 x.y - |x|^2 - |y|^2)/eps
__global__ __launch_bounds__(256) void k_gemm_ck(const float* __restrict__ X,
                                                 const float* __restrict__ Y) {
    __shared__ float As[16][128];
    __shared__ float Bs[16][128];
    int tid = threadIdx.x;
    int tx = tid & 15, ty = tid >> 4;
    int i0 = blockIdx.y * 128, j0 = blockIdx.x * 128;
    float acc[8][8];
#pragma unroll
    for (int m = 0; m < 8; m++)
#pragma unroll
        for (int n = 0; n < 8; n++) acc[m][n] = 0.f;

    for (int k0 = 0; k0 < DD; k0 += 16) {
#pragma unroll
        for (int q = 0; q < 2; q++) {
            int lt = tid + 256 * q;
            int row = lt >> 2, kq = (lt & 3) << 2;
            float4 a = *(const float4*)(X + (size_t)(i0 + row) * DD + k0 + kq);
            As[kq + 0][row] = a.x; As[kq + 1][row] = a.y;
            As[kq + 2][row] = a.z; As[kq + 3][row] = a.w;
            float4 b = *(const float4*)(Y + (size_t)(j0 + row) * DD + k0 + kq);
            Bs[kq + 0][row] = b.x; Bs[kq + 1][row] = b.y;
            Bs[kq + 2][row] = b.z; Bs[kq + 3][row] = b.w;
        }
        __syncthreads();
#pragma unroll
        for (int k = 0; k < 16; k++) {
            float af[8], bf[8];
#pragma unroll
            for (int m = 0; m < 8; m++) af[m] = As[k][ty * 8 + m];
#pragma unroll
            for (int n = 0; n < 8; n++) bf[n] = Bs[k][tx * 8 + n];
#pragma unroll
            for (int m = 0; m < 8; m++)
#pragma unroll
                for (int n = 0; n < 8; n++) acc[m][n] += af[m] * bf[n];
        }
        __syncthreads();
    }
#pragma unroll
    for (int m = 0; m < 8; m++) {
        int i = i0 + ty * 8 + m;
        float ri = g_r[i];
#pragma unroll
        for (int n0 = 0; n0 < 8; n0 += 4) {
            int j = j0 + tx * 8 + n0;
            float4 o;
            o.x = acc[m][n0 + 0] * (2.f * INV_EPS) - ri - g_c[j + 0];
            o.y = acc[m][n0 + 1] * (2.f * INV_EPS) - ri - g_c[j + 1];
            o.z = acc[m][n0 + 2] * (2.f * INV_EPS) - ri - g_c[j + 2];
            o.w = acc[m][n0 + 3] * (2.f * INV_EPS) - ri - g_c[j + 3];
            *(float4*)(g_Ck + (size_t)i * NQ + j) = o;
        }
    }
}

// ---------------------------------------------------------------- transpose Ck -> CkT
__global__ void k_transpose() {
    __shared__ float tile[32][33];
    int bx = blockIdx.x, by = blockIdx.y;
    int txl = threadIdx.x, tyl = threadIdx.y;
    int j = bx * 32 + txl;
#pragma unroll
    for (int r = tyl; r < 32; r += 8)
        tile[r][txl] = g_Ck[(size_t)(by * 32 + r) * NQ + j];
    __syncthreads();
    int i = by * 32 + txl;
#pragma unroll
    for (int r = tyl; r < 32; r += 8)
        g_CkT[(size_t)(bx * 32 + r) * NS + i] = tile[txl][r];
}

// ---------------------------------------------------------------- lse helpers
__device__ __forceinline__ void lse_combine(float& m, float& s, float om, float os) {
    float nm = fmaxf(m, om);
    s = s * __expf(m - nm) + os * __expf(om - nm);
    m = nm;
}

// ---------------------------------------------------------------- persistent Sinkhorn loop
__global__ __launch_bounds__(1024, 1) void k_sinkhorn() {
    __shared__ float4 s_vs4[NQ / 4];   // 32 KB
    __shared__ float4 s_us4[NS / 4];   // 4 KB
    __shared__ float sh_m[8][4], sh_s[8][4];
    __shared__ float s_err;
    __shared__ int s_brk;

    const int tid = threadIdx.x;
    const int warp = tid >> 5, lane = tid & 31;
    const int rg = warp >> 2;            // row-group 0..7
    const int l128 = tid & 127;          // lane within row-group
    const int row = blockIdx.x * 8 + rg; // row handled by this group (if < NS)
    const int gw = blockIdx.x * 32 + warp;
    int sense = 0;

    for (int t = 0; t < MAXIT; t++) {
        // ---- stage vs (L2 -> smem, bypass L1: written by other SMs last iter)
        for (int c = tid; c < NQ / 4; c += 1024)
            s_vs4[c] = __ldcg(((const float4*)g_vs) + c);
        if (tid == 0) s_err = 0.f;
        __syncthreads();

        // ---- row pass: u_new[row] = LOG_MU - lse_j(Ck[row][j] + vs[j])
        if (row < NS) {
            const float4* c4 = (const float4*)(g_Ck + (size_t)row * NQ);
            float m = -1e30f, s = 0.f;
#pragma unroll
            for (int c0 = 0; c0 < 16; c0 += 4) {
                float vb[16];
#pragma unroll
                for (int q = 0; q < 4; q++) {
                    float4 a = c4[l128 + 128 * (c0 + q)];
                    float4 b = s_vs4[l128 + 128 * (c0 + q)];
                    vb[4 * q + 0] = a.x + b.x; vb[4 * q + 1] = a.y + b.y;
                    vb[4 * q + 2] = a.z + b.z; vb[4 * q + 3] = a.w + b.w;
                }
                float mc = vb[0];
#pragma unroll
                for (int k = 1; k < 16; k++) mc = fmaxf(mc, vb[k]);
                float nm = fmaxf(m, mc);
                float sc = 0.f;
#pragma unroll
                for (int k = 0; k < 16; k++) sc += __expf(vb[k] - nm);
                s = s * __expf(m - nm) + sc;
                m = nm;
            }
#pragma unroll
            for (int o = 16; o; o >>= 1)
                lse_combine(m, s, __shfl_xor_sync(0xffffffffu, m, o),
                            __shfl_xor_sync(0xffffffffu, s, o));
            if (lane == 0) { sh_m[rg][warp & 3] = m; sh_s[rg][warp & 3] = s; }
        }
        __syncthreads();
        if (tid < 8) {
            int row2 = blockIdx.x * 8 + tid;
            if (row2 < NS) {
                float m = sh_m[tid][0], s = sh_s[tid][0];
#pragma unroll
                for (int q = 1; q < 4; q++) lse_combine(m, s, sh_m[tid][q], sh_s[tid][q]);
                float un = LOG_MU - (m + __logf(s));
                float uo = g_us[row2];   // only this SM ever touches this row
                g_us[row2] = un;
                atomicAdd(&s_err, EPS * fabsf(un - uo));
            }
        }
        __syncthreads();
        if (tid == 0 && blockIdx.x < 128) atomicAdd(&g_err[t], s_err);

        // ---- grid barrier 1 (us, err published)
        __threadfence();
        __syncthreads();
        if (tid == 0) {
            sense ^= 1;
            if (atomicAdd(&g_bar_count, 1) == NBLK - 1) {
                g_bar_count = 0;
                __threadfence();
                g_bar_sense = sense;
            } else {
                while (g_bar_sense != sense) __nanosleep(32);
                __threadfence();
            }
        }
        __syncthreads();

        // ---- stage us (written by other SMs)
        if (tid < NS / 4) s_us4[tid] = __ldcg(((const float4*)g_us) + tid);
        __syncthreads();

        // ---- col pass: vs[j] = LOG_NU - lse_i(CkT[j][i] + us[i])
#pragma unroll
        for (int rep = 0; rep < 2; rep++) {
            int j = gw + rep * NWARP_TOT;
            if (j < NQ) {
                const float4* c4 = (const float4*)(g_CkT + (size_t)j * NS);
                float m = -1e30f, s = 0.f;
#pragma unroll
                for (int c0 = 0; c0 < 8; c0 += 4) {
                    float vb[16];
#pragma unroll
                    for (int q = 0; q < 4; q++) {
                        float4 a = c4[lane + 32 * (c0 + q)];
                        float4 b = s_us4[lane + 32 * (c0 + q)];
                        vb[4 * q + 0] = a.x + b.x; vb[4 * q + 1] = a.y + b.y;
                        vb[4 * q + 2] = a.z + b.z; vb[4 * q + 3] = a.w + b.w;
                    }
                    float mc = vb[0];
#pragma unroll
                    for (int k = 1; k < 16; k++) mc = fmaxf(mc, vb[k]);
                    float nm = fmaxf(m, mc);
                    float sc = 0.f;
#pragma unroll
                    for (int k = 0; k < 16; k++) sc += __expf(vb[k] - nm);
                    s = s * __expf(m - nm) + sc;
                    m = nm;
                }
#pragma unroll
                for (int o = 16; o; o >>= 1)
                    lse_combine(m, s, __shfl_xor_sync(0xffffffffu, m, o),
                                __shfl_xor_sync(0xffffffffu, s, o));
                if (lane == 0) g_vs[j] = LOG_NU - (m + __logf(s));
            }
        }

        // ---- grid barrier 2 (vs published)
        __threadfence();
        __syncthreads();
        if (tid == 0) {
            sense ^= 1;
            if (atomicAdd(&g_bar_count, 1) == NBLK - 1) {
                g_bar_count = 0;
                __threadfence();
                g_bar_sense = sense;
            } else {
                while (g_bar_sense != sense) __nanosleep(32);
                __threadfence();
            }
        }
        __syncthreads();

        // ---- uniform convergence break (matches reference: updates of iter t applied)
        if (tid == 0) s_brk = (__ldcg(&g_err[t]) < THRESH) ? 1 : 0;
        __syncthreads();
        if (s_brk) break;
    }
}

// ---------------------------------------------------------------- final row lse -> g_ls
__global__ __launch_bounds__(256) void k_finallse() {
    int tid = threadIdx.x;
    int i = blockIdx.x;
    const float4* c4 = (const float4*)(g_Ck + (size_t)i * NQ);
    const float4* v4 = (const float4*)g_vs;
    float v[32];
#pragma unroll
    for (int sIdx = 0; sIdx < 8; sIdx++) {
        float4 a = c4[tid + 256 * sIdx];
        float4 b = v4[tid + 256 * sIdx];
        v[4 * sIdx + 0] = a.x + b.x; v[4 * sIdx + 1] = a.y + b.y;
        v[4 * sIdx + 2] = a.z + b.z; v[4 * sIdx + 3] = a.w + b.w;
    }
    float m = v[0];
#pragma unroll
    for (int k = 1; k < 32; k++) m = fmaxf(m, v[k]);
    float s = 0.f;
#pragma unroll
    for (int k = 0; k < 32; k++) s += __expf(v[k] - m);
#pragma unroll
    for (int o = 16; o; o >>= 1)
        lse_combine(m, s, __shfl_xor_sync(0xffffffffu, m, o), __shfl_xor_sync(0xffffffffu, s, o));
    __shared__ float sm[8], ss[8];
    int w = tid >> 5, l = tid & 31;
    if (l == 0) { sm[w] = m; ss[w] = s; }
    __syncthreads();
    if (w == 0) {
        m = sm[l & 7]; s = ss[l & 7];
#pragma unroll
        for (int o = 4; o; o >>= 1)
            lse_combine(m, s, __shfl_xor_sync(0xffffffffu, m, o), __shfl_xor_sync(0xffffffffu, s, o));
        if (l == 0) g_ls[i] = m + __logf(s);
    }
}

// ---------------------------------------------------------------- P = exp(Ck + vs - ls) in place
__global__ void k_makeP() {
    int idx = blockIdx.x * blockDim.x + threadIdx.x;
    int i = idx >> 11;
    int j4 = idx & 2047;
    float4 c = ((const float4*)g_Ck)[idx];
    float4 vv = ((const float4*)g_vs)[j4];
    float ls = g_ls[i];
    float4 o;
    o.x = __expf(c.x + vv.x - ls);
    o.y = __expf(c.y + vv.y - ls);
    o.z = __expf(c.z + vv.z - ls);
    o.w = __expf(c.w + vv.w - ls);
    ((float4*)g_Ck)[idx] = o;
}

// ---------------------------------------------------------------- O = P @ Y, split-K into g_CkT
#define SPLITK 4
__global__ __launch_bounds__(256) void k_outgemm(const float* __restrict__ Y) {
    __shared__ float As[16][64];
    __shared__ float Bs[16][64];
    int tid = threadIdx.x, tx = tid & 15, ty = tid >> 4;
    int bn = blockIdx.x, bm = blockIdx.y, ks = blockIdx.z;
    const float* P = g_Ck;
    float* part = g_CkT;
    float acc[4][4];
#pragma unroll
    for (int m = 0; m < 4; m++)
#pragma unroll
        for (int n = 0; n < 4; n++) acc[m][n] = 0.f;

    int prow = tid >> 2, pk = (tid & 3) << 2;
    int yrow = tid >> 4, yc = (tid & 15) << 2;
    int kbeg = ks * (NQ / SPLITK), kend = kbeg + NQ / SPLITK;
    for (int k0 = kbeg; k0 < kend; k0 += 16) {
        float4 a = *(const float4*)(P + (size_t)(bm * 64 + prow) * NQ + k0 + pk);
        As[pk + 0][prow] = a.x; As[pk + 1][prow] = a.y;
        As[pk + 2][prow] = a.z; As[pk + 3][prow] = a.w;
        float4 b = *(const float4*)(Y + (size_t)(k0 + yrow) * DD + bn * 64 + yc);
        *(float4*)&Bs[yrow][yc] = b;
        __syncthreads();
#pragma unroll
        for (int k = 0; k < 16; k++) {
            float af[4], bf[4];
#pragma unroll
            for (int m = 0; m < 4; m++) af[m] = As[k][ty * 4 + m];
#pragma unroll
            for (int n = 0; n < 4; n++) bf[n] = Bs[k][tx * 4 + n];
#pragma unroll
            for (int m = 0; m < 4; m++)
#pragma unroll
                for (int n = 0; n < 4; n++) acc[m][n] += af[m] * bf[n];
        }
        __syncthreads();
    }
#pragma unroll
    for (int m = 0; m < 4; m++) {
        float4 o;
        o.x = acc[m][0]; o.y = acc[m][1]; o.z = acc[m][2]; o.w = acc[m][3];
        *(float4*)(part + (size_t)ks * NS * DD + (size_t)(bm * 64 + ty * 4 + m) * DD + bn * 64 + tx * 4) = o;
    }
}

// ---------------------------------------------------------------- reduce split-K + append z_query
__global__ void k_finalize(float* __restrict__ out, const float* __restrict__ Y) {
    int idx = blockIdx.x * blockDim.x + threadIdx.x;
    const float4* part = (const float4*)g_CkT;
    float4* o4 = (float4*)out;
    if (idx < NS * DD / 4) {
        float4 a = part[idx], b = part[idx + 65536], c = part[idx + 131072], d = part[idx + 196608];
        float4 r;
        r.x = a.x + b.x + c.x + d.x;
        r.y = a.y + b.y + c.y + d.y;
        r.z = a.z + b.z + c.z + d.z;
        r.w = a.w + b.w + c.w + d.w;
        o4[idx] = r;
    } else {
        o4[idx] = ((const float4*)Y)[idx - NS * DD / 4];
    }
}

// ----------------------------------------------------------------
extern "C" void kernel_launch(void* const* d_in, const int* in_sizes, int n_in,
                              void* d_out, int out_size) {
    const float* zs = (const float*)d_in[0];
    const float* zq = (const float*)d_in[1];
    if (n_in >= 2 && in_sizes[0] == NQ * DD && in_sizes[1] == NS * DD) {
        const float* t = zs; zs = zq; zq = t;
    }
    k_init<<<1, 1024>>>();
    k_norms<<<(NS + NQ) * 32 / 256, 256>>>(zs, zq);
    k_gemm_ck<<<dim3(NQ / 128, NS / 128), 256>>>(zs, zq);
    k_transpose<<<dim3(NQ / 32, NS / 32), dim3(32, 8)>>>();
    k_sinkhorn<<<NBLK, 1024>>>();
    k_finallse<<<NS, 256>>>();
    k_makeP<<<NS * NQ / 4 / 256, 256>>>();
    k_outgemm<<<dim3(DD / 64, NS / 64, SPLITK), 256>>>(zq);
    k_finalize<<<(NS + NQ) * DD / 4 / 256, 256>>>((float*)d_out, zq);
}